// round 4
// baseline (speedup 1.0000x reference)
#include <cuda_runtime.h>
#include <math.h>
#include <stdint.h>

#define R 128        // B*H = 8*16
#define D 256        // head dim
#define M 65536      // memory slots
#define NUM_TOP 16
#define NUM_RAND 4

// ---------------- scratch (device globals; no allocations) ----------------
__device__ float g_logits[(size_t)R * M];     // 32 MB
__device__ float g_top_val[R * NUM_TOP];
__device__ int   g_top_idx[R * NUM_TOP];
__device__ int   g_excluded[M];
__device__ int   g_rand_idx[NUM_RAND];

// ---------------- fp32 GEMM: logits[r][m] = dot(q[r], key[m]) ----------------
#define BK 32
#define KST (BK + 4)   // 36 floats stride: float4-aligned, conflict-light

__global__ __launch_bounds__(256) void gemm_kernel(const float* __restrict__ q,
                                                   const float* __restrict__ key) {
    __shared__ float qs[R * KST];     // [row][k] chunk
    __shared__ float ks[128 * KST];   // [col][k] chunk
    const int tid = threadIdx.x;
    const int tx = tid & 15;
    const int ty = tid >> 4;
    const int cb = blockIdx.x * 128;

    float acc[8][8];
#pragma unroll
    for (int i = 0; i < 8; i++)
#pragma unroll
        for (int j = 0; j < 8; j++) acc[i][j] = 0.0f;

    for (int k0 = 0; k0 < D; k0 += BK) {
#pragma unroll
        for (int it = 0; it < 4; it++) {
            int f4 = tid + it * 256;
            int row = f4 >> 3;
            int c4 = f4 & 7;
            float4 v = *reinterpret_cast<const float4*>(q + row * D + k0 + c4 * 4);
            float* dst = &qs[row * KST + c4 * 4];
            dst[0] = v.x; dst[1] = v.y; dst[2] = v.z; dst[3] = v.w;
        }
#pragma unroll
        for (int it = 0; it < 4; it++) {
            int f4 = tid + it * 256;
            int col = f4 >> 3;
            int c4 = f4 & 7;
            float4 v = *reinterpret_cast<const float4*>(key + (size_t)(cb + col) * D + k0 + c4 * 4);
            float* dst = &ks[col * KST + c4 * 4];
            dst[0] = v.x; dst[1] = v.y; dst[2] = v.z; dst[3] = v.w;
        }
        __syncthreads();

#pragma unroll
        for (int kk = 0; kk < BK; kk += 4) {
            float4 a4[8], b4[8];
#pragma unroll
            for (int i = 0; i < 8; i++)
                a4[i] = *reinterpret_cast<const float4*>(&qs[(ty * 8 + i) * KST + kk]);
#pragma unroll
            for (int j = 0; j < 8; j++)
                b4[j] = *reinterpret_cast<const float4*>(&ks[(tx + 16 * j) * KST + kk]);
#pragma unroll
            for (int i = 0; i < 8; i++)
#pragma unroll
                for (int j = 0; j < 8; j++) {
                    acc[i][j] = fmaf(a4[i].x, b4[j].x, acc[i][j]);
                    acc[i][j] = fmaf(a4[i].y, b4[j].y, acc[i][j]);
                    acc[i][j] = fmaf(a4[i].z, b4[j].z, acc[i][j]);
                    acc[i][j] = fmaf(a4[i].w, b4[j].w, acc[i][j]);
                }
        }
        __syncthreads();
    }

#pragma unroll
    for (int i = 0; i < 8; i++) {
        int row = ty * 8 + i;
#pragma unroll
        for (int j = 0; j < 8; j++) {
            int col = cb + tx + 16 * j;
            g_logits[(size_t)row * M + col] = acc[i][j];
        }
    }
}

// ---------------- per-row top-16 (descending, tie -> lower index) ----------------
__global__ __launch_bounds__(256) void topk_kernel() {
    const int row = blockIdx.x;
    const int tid = threadIdx.x;
    float lv[NUM_TOP];
    int li[NUM_TOP];
#pragma unroll
    for (int j = 0; j < NUM_TOP; j++) { lv[j] = -INFINITY; li[j] = 0x7FFFFFFF; }

    const float* lp = g_logits + (size_t)row * M;
    for (int m = tid; m < M; m += 256) {
        float v = lp[m];
        if (v > lv[NUM_TOP - 1]) {
            float cv = v; int ci = m;
#pragma unroll
            for (int j = 0; j < NUM_TOP; j++) {
                if (cv > lv[j]) {
                    float tv = lv[j]; lv[j] = cv; cv = tv;
                    int ti = li[j]; li[j] = ci; ci = ti;
                }
            }
        }
    }

    __shared__ float sv[256 * NUM_TOP];
    __shared__ int   si[256 * NUM_TOP];
#pragma unroll
    for (int j = 0; j < NUM_TOP; j++) { sv[tid * NUM_TOP + j] = lv[j]; si[tid * NUM_TOP + j] = li[j]; }
    __syncthreads();

    for (int s = 128; s >= 1; s >>= 1) {
        if (tid < s) {
            const float* av = &sv[tid * NUM_TOP];
            const int*   ai = &si[tid * NUM_TOP];
            const float* bv = &sv[(tid + s) * NUM_TOP];
            const int*   bi = &si[(tid + s) * NUM_TOP];
            float ov[NUM_TOP]; int oi[NUM_TOP];
            int p = 0, qq = 0;
#pragma unroll
            for (int j = 0; j < NUM_TOP; j++) {
                bool ta;
                if (p >= NUM_TOP)       ta = false;          // a exhausted
                else if (qq >= NUM_TOP) ta = true;           // b exhausted
                else {
                    float va = av[p], vb = bv[qq];
                    ta = (va > vb) || (va == vb && ai[p] < bi[qq]);
                }
                if (ta) { ov[j] = av[p]; oi[j] = ai[p]; p++; }
                else    { ov[j] = bv[qq]; oi[j] = bi[qq]; qq++; }
            }
#pragma unroll
            for (int j = 0; j < NUM_TOP; j++) { sv[tid * NUM_TOP + j] = ov[j]; si[tid * NUM_TOP + j] = oi[j]; }
        }
        __syncthreads();
    }

    if (tid < NUM_TOP) {
        g_top_val[row * NUM_TOP + tid] = sv[tid];
        g_top_idx[row * NUM_TOP + tid] = si[tid];
    }
}

// ---------------- exclusion mask ----------------
__global__ void zero_excl_kernel() {
    int i = blockIdx.x * 256 + threadIdx.x;
    if (i < M) g_excluded[i] = 0;
}

__global__ void scatter_excl_kernel() {
    int t = blockIdx.x * 256 + threadIdx.x;   // 2048 total
    if (t < R * NUM_TOP) g_excluded[g_top_idx[t]] = 1;
}

// ---------------- threefry2x32, PARTITIONABLE counter scheme ----------------
// element i: cipher input (x0, x1) = (hi64(i), lo64(i)) = (0, i); key = (0, 42)
// bit_width<64 path: bits = x0out ^ x1out  (XOR fold of both output lanes)
__device__ __forceinline__ uint32_t rotl32(uint32_t x, int r) { return (x << r) | (x >> (32 - r)); }

#define TF_GROUP(a,b,c,d) \
    x0 += x1; x1 = rotl32(x1, a); x1 ^= x0; \
    x0 += x1; x1 = rotl32(x1, b); x1 ^= x0; \
    x0 += x1; x1 = rotl32(x1, c); x1 ^= x0; \
    x0 += x1; x1 = rotl32(x1, d); x1 ^= x0;

__global__ __launch_bounds__(1024) void rand_kernel() {
    const int tid = threadIdx.x;
    const uint32_t ks0 = 0u, ks1 = 42u, ks2 = 0x1BD11BDAu ^ 42u;

    unsigned long long best[NUM_RAND];
#pragma unroll
    for (int j = 0; j < NUM_RAND; j++) best[j] = 0xFFFFFFFFFFFFFFFFull;

    for (int i = tid; i < M; i += 1024) {
        uint32_t x0 = 0u + ks0;            // counts_hi = 0
        uint32_t x1 = (uint32_t)i + ks1;   // counts_lo = i
        TF_GROUP(13, 15, 26, 6);  x0 += ks1; x1 += ks2 + 1u;
        TF_GROUP(17, 29, 16, 24); x0 += ks2; x1 += ks0 + 2u;
        TF_GROUP(13, 15, 26, 6);  x0 += ks0; x1 += ks1 + 3u;
        TF_GROUP(17, 29, 16, 24); x0 += ks1; x1 += ks2 + 4u;
        TF_GROUP(13, 15, 26, 6);  x0 += ks2; x1 += ks0 + 5u;
        uint32_t bits = x0 ^ x1;           // partitionable <64-bit combine: XOR both lanes
        uint32_t fb = g_excluded[i] ? 0x7F800000u : ((bits >> 9) | 0x3F800000u);
        unsigned long long kv = ((unsigned long long)fb << 32) | (uint32_t)i;
        if (kv < best[NUM_RAND - 1]) {
            unsigned long long c = kv;
#pragma unroll
            for (int j = 0; j < NUM_RAND; j++) {
                if (c < best[j]) { unsigned long long t = best[j]; best[j] = c; c = t; }
            }
        }
    }

    __shared__ unsigned long long sk[1024 * NUM_RAND];
#pragma unroll
    for (int j = 0; j < NUM_RAND; j++) sk[tid * NUM_RAND + j] = best[j];
    __syncthreads();

    for (int s = 512; s >= 1; s >>= 1) {
        if (tid < s) {
            const unsigned long long* a = &sk[tid * NUM_RAND];
            const unsigned long long* b = &sk[(tid + s) * NUM_RAND];
            unsigned long long o[NUM_RAND];
            int p = 0, qq = 0;
#pragma unroll
            for (int j = 0; j < NUM_RAND; j++) {
                bool ta;
                if (p >= NUM_RAND)       ta = false;
                else if (qq >= NUM_RAND) ta = true;
                else                     ta = (a[p] < b[qq]);
                if (ta) { o[j] = a[p]; p++; }
                else    { o[j] = b[qq]; qq++; }
            }
#pragma unroll
            for (int j = 0; j < NUM_RAND; j++) sk[tid * NUM_RAND + j] = o[j];
        }
        __syncthreads();
    }

    if (tid < NUM_RAND) g_rand_idx[tid] = (int)(sk[tid] & 0xFFFFFFFFu);
}

// ---------------- composite + softmax + output ----------------
__global__ __launch_bounds__(32) void final_kernel(const float* __restrict__ q,
                                                   const float* __restrict__ key,
                                                   float* __restrict__ out) {
    const int row = blockIdx.x;
    const int lane = threadIdx.x;
    __shared__ float rl[NUM_RAND];

    const float* qp = q + (size_t)row * D;
#pragma unroll
    for (int j = 0; j < NUM_RAND; j++) {
        int idx = g_rand_idx[j];
        const float* kp = key + (size_t)idx * D;
        float s = 0.0f;
        for (int d = lane; d < D; d += 32) s = fmaf(qp[d], kp[d], s);
#pragma unroll
        for (int o = 16; o; o >>= 1) s += __shfl_xor_sync(0xFFFFFFFFu, s, o);
        if (lane == 0) rl[j] = s;
    }
    __syncwarp();

    if (lane == 0) {
        const int NC = NUM_TOP + NUM_RAND;  // 20
        float cl[NC]; int ci[NC];
#pragma unroll
        for (int j = 0; j < NUM_TOP; j++) {
            cl[j] = g_top_val[row * NUM_TOP + j];
            ci[j] = g_top_idx[row * NUM_TOP + j];
        }
#pragma unroll
        for (int j = 0; j < NUM_RAND; j++) {
            cl[NUM_TOP + j] = rl[j];
            ci[NUM_TOP + j] = g_rand_idx[j];
        }
        float mx = cl[0];
#pragma unroll
        for (int j = 1; j < NC; j++) mx = fmaxf(mx, cl[j]);
        float e[NC]; float sum = 0.0f;
#pragma unroll
        for (int j = 0; j < NC; j++) { e[j] = expf(cl[j] - mx); sum += e[j]; }
        float inv = 1.0f / sum;
#pragma unroll
        for (int j = 0; j < NC; j++) {
            out[row * NC + j] = (float)ci[j];                 // composite_idx (as f32)
            out[R * NC + row * NC + j] = e[j] * inv;          // composite_probs
        }
    }
}

// ---------------- launcher ----------------
extern "C" void kernel_launch(void* const* d_in, const int* in_sizes, int n_in,
                              void* d_out, int out_size) {
    const float* q   = (const float*)d_in[0];   // (8,16,256)
    const float* key = (const float*)d_in[1];   // (65536,256)
    float* out = (float*)d_out;

    gemm_kernel<<<M / 128, 256>>>(q, key);
    topk_kernel<<<R, 256>>>();
    zero_excl_kernel<<<M / 256, 256>>>();
    scatter_excl_kernel<<<(R * NUM_TOP + 255) / 256, 256>>>();
    rand_kernel<<<1, 1024>>>();
    final_kernel<<<R, 32>>>(q, key, out);
}

// round 5
// speedup vs baseline: 1.9072x; 1.9072x over previous
#include <cuda_runtime.h>
#include <math.h>
#include <stdint.h>

#define R 128        // B*H = 8*16
#define D 256        // head dim
#define M 65536      // memory slots
#define NUM_TOP 16
#define NUM_RAND 4
#define NCHUNK 4
#define CHUNK (M / NCHUNK)      // 16384
#define CAND_K 24               // per-chunk candidates
#define NCAND (NCHUNK * CAND_K) // 96 per row

// ---------------- scratch (device globals; no allocations) ----------------
__device__ float g_logits[(size_t)R * M];       // 32 MB (tf32-accurate)
__device__ int   g_cand_idx[R * NCAND];
__device__ float g_top_val[R * NUM_TOP];        // exact fp32 after rescore
__device__ int   g_top_idx[R * NUM_TOP];
__device__ int   g_excluded[M];
__device__ unsigned long long g_rand_part[8 * NUM_RAND];
__device__ int   g_rand_idx[NUM_RAND];

// ---------------- tf32 helpers ----------------
__device__ __forceinline__ uint32_t f2tf32(float f) {
    uint32_t r;
    asm("cvt.rna.tf32.f32 %0, %1;" : "=r"(r) : "f"(f));
    return r;
}

__device__ __forceinline__ void mma_tf32(float* c, const uint32_t* a, uint32_t b0, uint32_t b1) {
    asm volatile(
        "mma.sync.aligned.m16n8k8.row.col.f32.tf32.tf32.f32 "
        "{%0,%1,%2,%3}, {%4,%5,%6,%7}, {%8,%9}, {%0,%1,%2,%3};"
        : "+f"(c[0]), "+f"(c[1]), "+f"(c[2]), "+f"(c[3])
        : "r"(a[0]), "r"(a[1]), "r"(a[2]), "r"(a[3]), "r"(b0), "r"(b1));
}

// ---------------- tf32 candidate GEMM: 128 rows x 64 cols per block ----------------
#define GCOLS 64
#define KCH 128            // K chunk held in smem
#define KSTRIDE 132        // floats per col in smem (132 % 32 == 4 -> conflict-free frag loads)

__global__ __launch_bounds__(256) void gemm_tf32_kernel(const float* __restrict__ q,
                                                        const float* __restrict__ key) {
    __shared__ float ks[GCOLS * KSTRIDE];   // 33.8 KB, [col][k] (tf32 bits)
    const int tid = threadIdx.x;
    const int lane = tid & 31;
    const int warp = tid >> 5;
    const int cb = blockIdx.x * GCOLS;

    float acc[8][4];
#pragma unroll
    for (int j = 0; j < 8; j++)
#pragma unroll
        for (int e = 0; e < 4; e++) acc[j][e] = 0.0f;

    const int r0 = warp * 16 + (lane >> 2);
    const int cc = lane & 3;

    for (int kb = 0; kb < D / KCH; kb++) {
        // load + tf32-convert B chunk: 64 cols x 128 k = 2048 float4
#pragma unroll
        for (int it = 0; it < 8; it++) {
            int f4 = tid + it * 256;
            int col = f4 >> 5;          // 32 float4 per col
            int k4 = f4 & 31;
            float4 v = *reinterpret_cast<const float4*>(key + (size_t)(cb + col) * D + kb * KCH + k4 * 4);
            float4 w;
            w.x = __uint_as_float(f2tf32(v.x));
            w.y = __uint_as_float(f2tf32(v.y));
            w.z = __uint_as_float(f2tf32(v.z));
            w.w = __uint_as_float(f2tf32(v.w));
            *reinterpret_cast<float4*>(&ks[col * KSTRIDE + k4 * 4]) = w;
        }
        __syncthreads();

#pragma unroll
        for (int kc = 0; kc < 2; kc++) {
            // A fragments for this 64-k subchunk (from global; q is L1-hot)
            uint32_t af[8][4];
#pragma unroll
            for (int i = 0; i < 8; i++) {
                int k = kb * KCH + kc * 64 + i * 8 + cc;
                af[i][0] = f2tf32(q[r0 * D + k]);
                af[i][1] = f2tf32(q[(r0 + 8) * D + k]);
                af[i][2] = f2tf32(q[r0 * D + k + 4]);
                af[i][3] = f2tf32(q[(r0 + 8) * D + k + 4]);
            }
#pragma unroll
            for (int j = 0; j < 8; j++) {
                const float* bp = &ks[(j * 8 + (lane >> 2)) * KSTRIDE + kc * 64 + cc];
#pragma unroll
                for (int i = 0; i < 8; i++) {
                    uint32_t b0 = __float_as_uint(bp[i * 8]);
                    uint32_t b1 = __float_as_uint(bp[i * 8 + 4]);
                    mma_tf32(acc[j], af[i], b0, b1);
                }
            }
        }
        __syncthreads();
    }

    // store C: c0/c1 at (row, 2c), (row, 2c+1); c2/c3 at row+8
    const int orow = warp * 16 + (lane >> 2);
    const int ocol = cb + (lane & 3) * 2;
#pragma unroll
    for (int j = 0; j < 8; j++) {
        g_logits[(size_t)orow * M + ocol + j * 8]           = acc[j][0];
        g_logits[(size_t)orow * M + ocol + j * 8 + 1]       = acc[j][1];
        g_logits[(size_t)(orow + 8) * M + ocol + j * 8]     = acc[j][2];
        g_logits[(size_t)(orow + 8) * M + ocol + j * 8 + 1] = acc[j][3];
    }
}

// ---------------- per-(row,chunk) top-24 candidates from tf32 scores ----------------
// monotone descending key: larger value -> smaller u64; tie -> smaller idx
__device__ __forceinline__ unsigned long long desc_key(float v, int idx) {
    uint32_t u = __float_as_uint(v);
    uint32_t mono = (u & 0x80000000u) ? ~u : (u | 0x80000000u);  // ascending order
    uint32_t ord = ~mono;                                        // descending
    return ((unsigned long long)ord << 32) | (uint32_t)idx;
}

__global__ __launch_bounds__(256) void cand_kernel() {
    const int bid = blockIdx.x;          // 512 blocks
    const int row = bid >> 2;
    const int chunk = bid & 3;
    const int tid = threadIdx.x;

    unsigned long long lv[CAND_K];
#pragma unroll
    for (int j = 0; j < CAND_K; j++) lv[j] = 0xFFFFFFFFFFFFFFFFull;

    const float* lp = g_logits + (size_t)row * M + chunk * CHUNK;
    for (int m = tid; m < CHUNK; m += 256) {
        unsigned long long k = desc_key(lp[m], chunk * CHUNK + m);
        if (k < lv[CAND_K - 1]) {
            unsigned long long c = k;
#pragma unroll
            for (int j = 0; j < CAND_K; j++) {
                if (c < lv[j]) { unsigned long long t = lv[j]; lv[j] = c; c = t; }
            }
        }
    }

    __shared__ unsigned long long sk[256 * CAND_K];   // 48 KB
#pragma unroll
    for (int j = 0; j < CAND_K; j++) sk[tid * CAND_K + j] = lv[j];
    __syncthreads();

    for (int s = 128; s >= 1; s >>= 1) {
        if (tid < s) {
            const unsigned long long* a = &sk[tid * CAND_K];
            const unsigned long long* b = &sk[(tid + s) * CAND_K];
            unsigned long long o[CAND_K];
            int p = 0, qq = 0;
#pragma unroll
            for (int j = 0; j < CAND_K; j++) {
                bool ta;
                if (p >= CAND_K)       ta = false;
                else if (qq >= CAND_K) ta = true;
                else                   ta = (a[p] < b[qq]);
                if (ta) { o[j] = a[p]; p++; }
                else    { o[j] = b[qq]; qq++; }
            }
#pragma unroll
            for (int j = 0; j < CAND_K; j++) sk[tid * CAND_K + j] = o[j];
        }
        __syncthreads();
    }

    if (tid < CAND_K)
        g_cand_idx[row * NCAND + chunk * CAND_K + tid] = (int)(sk[tid] & 0xFFFFFFFFu);
}

// ---------------- exact fp32 rescore of 96 candidates + exact top-16 ----------------
__global__ __launch_bounds__(128) void rescore_kernel(const float* __restrict__ q,
                                                      const float* __restrict__ key) {
    const int row = blockIdx.x;
    const int tid = threadIdx.x;
    const int warp = tid >> 5;
    const int lane = tid & 31;

    __shared__ float sval[NCAND];
    __shared__ int   sidx[NCAND];

    float qv[8];
#pragma unroll
    for (int u = 0; u < 8; u++) qv[u] = q[(size_t)row * D + lane + 32 * u];

    for (int c = warp; c < NCAND; c += 4) {
        int idx = g_cand_idx[row * NCAND + c];
        const float* kp = key + (size_t)idx * D;
        float s = 0.0f;
#pragma unroll
        for (int u = 0; u < 8; u++) s = fmaf(qv[u], kp[lane + 32 * u], s);
#pragma unroll
        for (int o = 16; o; o >>= 1) s += __shfl_xor_sync(0xFFFFFFFFu, s, o);
        if (lane == 0) { sval[c] = s; sidx[c] = idx; }
    }
    __syncthreads();

    if (tid == 0) {
        float lv[NUM_TOP]; int li[NUM_TOP];
#pragma unroll
        for (int j = 0; j < NUM_TOP; j++) { lv[j] = -INFINITY; li[j] = 0x7FFFFFFF; }
        for (int c = 0; c < NCAND; c++) {
            float v = sval[c]; int idx = sidx[c];
            bool better_last = (v > lv[NUM_TOP - 1]) ||
                               (v == lv[NUM_TOP - 1] && idx < li[NUM_TOP - 1]);
            if (better_last) {
                float cv = v; int ci = idx;
#pragma unroll
                for (int j = 0; j < NUM_TOP; j++) {
                    if (cv > lv[j] || (cv == lv[j] && ci < li[j])) {
                        float tv = lv[j]; lv[j] = cv; cv = tv;
                        int ti = li[j]; li[j] = ci; ci = ti;
                    }
                }
            }
        }
#pragma unroll
        for (int j = 0; j < NUM_TOP; j++) {
            g_top_val[row * NUM_TOP + j] = lv[j];
            g_top_idx[row * NUM_TOP + j] = li[j];
        }
    }
}

// ---------------- exclusion mask ----------------
__global__ void zero_excl_kernel() {
    int i = blockIdx.x * 256 + threadIdx.x;
    if (i < M) g_excluded[i] = 0;
}

__global__ void scatter_excl_kernel() {
    int t = blockIdx.x * 256 + threadIdx.x;   // 2048 total
    if (t < R * NUM_TOP) g_excluded[g_top_idx[t]] = 1;
}

// ---------------- threefry2x32, partitionable: bits = x0out ^ x1out ----------------
__device__ __forceinline__ uint32_t rotl32(uint32_t x, int r) { return (x << r) | (x >> (32 - r)); }

#define TF_GROUP(a,b,c,d) \
    x0 += x1; x1 = rotl32(x1, a); x1 ^= x0; \
    x0 += x1; x1 = rotl32(x1, b); x1 ^= x0; \
    x0 += x1; x1 = rotl32(x1, c); x1 ^= x0; \
    x0 += x1; x1 = rotl32(x1, d); x1 ^= x0;

__global__ __launch_bounds__(1024) void rand_part_kernel() {
    const int tid = threadIdx.x;
    const int base = blockIdx.x * (M / 8);   // 8192 per block
    const uint32_t ks0 = 0u, ks1 = 42u, ks2 = 0x1BD11BDAu ^ 42u;

    unsigned long long best[NUM_RAND];
#pragma unroll
    for (int j = 0; j < NUM_RAND; j++) best[j] = 0xFFFFFFFFFFFFFFFFull;

    for (int i = base + tid; i < base + M / 8; i += 1024) {
        uint32_t x0 = 0u + ks0;            // counts_hi = 0
        uint32_t x1 = (uint32_t)i + ks1;   // counts_lo = i
        TF_GROUP(13, 15, 26, 6);  x0 += ks1; x1 += ks2 + 1u;
        TF_GROUP(17, 29, 16, 24); x0 += ks2; x1 += ks0 + 2u;
        TF_GROUP(13, 15, 26, 6);  x0 += ks0; x1 += ks1 + 3u;
        TF_GROUP(17, 29, 16, 24); x0 += ks1; x1 += ks2 + 4u;
        TF_GROUP(13, 15, 26, 6);  x0 += ks2; x1 += ks0 + 5u;
        uint32_t bits = x0 ^ x1;           // partitionable <64-bit combine
        uint32_t fb = g_excluded[i] ? 0x7F800000u : ((bits >> 9) | 0x3F800000u);
        unsigned long long kv = ((unsigned long long)fb << 32) | (uint32_t)i;
        if (kv < best[NUM_RAND - 1]) {
            unsigned long long c = kv;
#pragma unroll
            for (int j = 0; j < NUM_RAND; j++) {
                if (c < best[j]) { unsigned long long t = best[j]; best[j] = c; c = t; }
            }
        }
    }

    __shared__ unsigned long long sk[1024 * NUM_RAND];
#pragma unroll
    for (int j = 0; j < NUM_RAND; j++) sk[tid * NUM_RAND + j] = best[j];
    __syncthreads();

    for (int s = 512; s >= 1; s >>= 1) {
        if (tid < s) {
            const unsigned long long* a = &sk[tid * NUM_RAND];
            const unsigned long long* b = &sk[(tid + s) * NUM_RAND];
            unsigned long long o[NUM_RAND];
            int p = 0, qq = 0;
#pragma unroll
            for (int j = 0; j < NUM_RAND; j++) {
                bool ta;
                if (p >= NUM_RAND)       ta = false;
                else if (qq >= NUM_RAND) ta = true;
                else                     ta = (a[p] < b[qq]);
                if (ta) { o[j] = a[p]; p++; }
                else    { o[j] = b[qq]; qq++; }
            }
#pragma unroll
            for (int j = 0; j < NUM_RAND; j++) sk[tid * NUM_RAND + j] = o[j];
        }
        __syncthreads();
    }

    if (tid < NUM_RAND) g_rand_part[blockIdx.x * NUM_RAND + tid] = sk[tid];
}

__global__ void rand_merge_kernel() {
    if (threadIdx.x == 0) {
        unsigned long long best[NUM_RAND];
#pragma unroll
        for (int j = 0; j < NUM_RAND; j++) best[j] = 0xFFFFFFFFFFFFFFFFull;
        for (int i = 0; i < 8 * NUM_RAND; i++) {
            unsigned long long c = g_rand_part[i];
            if (c < best[NUM_RAND - 1]) {
#pragma unroll
                for (int j = 0; j < NUM_RAND; j++) {
                    if (c < best[j]) { unsigned long long t = best[j]; best[j] = c; c = t; }
                }
            }
        }
#pragma unroll
        for (int j = 0; j < NUM_RAND; j++) g_rand_idx[j] = (int)(best[j] & 0xFFFFFFFFu);
    }
}

// ---------------- composite + softmax + output ----------------
__global__ __launch_bounds__(32) void final_kernel(const float* __restrict__ q,
                                                   const float* __restrict__ key,
                                                   float* __restrict__ out) {
    const int row = blockIdx.x;
    const int lane = threadIdx.x;
    __shared__ float rl[NUM_RAND];

    const float* qp = q + (size_t)row * D;
#pragma unroll
    for (int j = 0; j < NUM_RAND; j++) {
        int idx = g_rand_idx[j];
        const float* kp = key + (size_t)idx * D;
        float s = 0.0f;
        for (int d = lane; d < D; d += 32) s = fmaf(qp[d], kp[d], s);
#pragma unroll
        for (int o = 16; o; o >>= 1) s += __shfl_xor_sync(0xFFFFFFFFu, s, o);
        if (lane == 0) rl[j] = s;
    }
    __syncwarp();

    if (lane == 0) {
        const int NC = NUM_TOP + NUM_RAND;  // 20
        float cl[NC]; int ci[NC];
#pragma unroll
        for (int j = 0; j < NUM_TOP; j++) {
            cl[j] = g_top_val[row * NUM_TOP + j];
            ci[j] = g_top_idx[row * NUM_TOP + j];
        }
#pragma unroll
        for (int j = 0; j < NUM_RAND; j++) {
            cl[NUM_TOP + j] = rl[j];
            ci[NUM_TOP + j] = g_rand_idx[j];
        }
        float mx = cl[0];
#pragma unroll
        for (int j = 1; j < NC; j++) mx = fmaxf(mx, cl[j]);
        float e[NC]; float sum = 0.0f;
#pragma unroll
        for (int j = 0; j < NC; j++) { e[j] = expf(cl[j] - mx); sum += e[j]; }
        float inv = 1.0f / sum;
#pragma unroll
        for (int j = 0; j < NC; j++) {
            out[row * NC + j] = (float)ci[j];                 // composite_idx (as f32)
            out[R * NC + row * NC + j] = e[j] * inv;          // composite_probs
        }
    }
}

// ---------------- launcher ----------------
extern "C" void kernel_launch(void* const* d_in, const int* in_sizes, int n_in,
                              void* d_out, int out_size) {
    const float* q   = (const float*)d_in[0];   // (8,16,256)
    const float* key = (const float*)d_in[1];   // (65536,256)
    float* out = (float*)d_out;

    zero_excl_kernel<<<M / 256, 256>>>();
    gemm_tf32_kernel<<<M / GCOLS, 256>>>(q, key);
    cand_kernel<<<R * NCHUNK, 256>>>();
    rescore_kernel<<<R, 128>>>(q, key);
    scatter_excl_kernel<<<(R * NUM_TOP + 255) / 256, 256>>>();
    rand_part_kernel<<<8, 1024>>>();
    rand_merge_kernel<<<1, 32>>>();
    final_kernel<<<R, 32>>>(q, key, out);
}

// round 6
// speedup vs baseline: 2.1593x; 1.1322x over previous
#include <cuda_runtime.h>
#include <math.h>
#include <stdint.h>

#define R 128        // B*H = 8*16
#define D 256        // head dim
#define M 65536      // memory slots
#define NUM_TOP 16
#define NUM_RAND 4
#define NCHUNK 4
#define CHUNK (M / NCHUNK)      // 16384
#define CAND_K 24               // per-chunk candidates
#define NCAND (NCHUNK * CAND_K) // 96 per row

// ---------------- scratch (device globals; no allocations) ----------------
__device__ float g_logits[(size_t)R * M];       // 32 MB (bf16-accurate)
__device__ uint32_t g_qbf[R * (D / 2)];         // q as bf16x2 pairs, 64 KB
__device__ int   g_cand_idx[R * NCAND];
__device__ float g_top_val[R * NUM_TOP];        // exact fp32 after rescore
__device__ int   g_top_idx[R * NUM_TOP];
__device__ int   g_excluded[M];
__device__ unsigned long long g_rand_part[8 * NUM_RAND];
__device__ int   g_rand_idx[NUM_RAND];

// ---------------- bf16 helpers ----------------
__device__ __forceinline__ uint32_t packbf(float lo, float hi) {
    uint32_t r;
    asm("cvt.rn.bf16x2.f32 %0, %1, %2;" : "=r"(r) : "f"(hi), "f"(lo));  // first src -> high half
    return r;
}

__device__ __forceinline__ void mma_bf16(float* c, const uint32_t* a, uint32_t b0, uint32_t b1) {
    asm volatile(
        "mma.sync.aligned.m16n8k16.row.col.f32.bf16.bf16.f32 "
        "{%0,%1,%2,%3}, {%4,%5,%6,%7}, {%8,%9}, {%0,%1,%2,%3};"
        : "+f"(c[0]), "+f"(c[1]), "+f"(c[2]), "+f"(c[3])
        : "r"(a[0]), "r"(a[1]), "r"(a[2]), "r"(a[3]), "r"(b0), "r"(b1));
}

// ---------------- q -> bf16x2 pre-conversion (one-shot, 16384 words) ----------------
__global__ __launch_bounds__(512) void qconv_kernel(const float* __restrict__ q) {
    int t = blockIdx.x * 512 + threadIdx.x;   // 32 blocks? 16384 words -> grid 32
    if (t < R * (D / 2)) {
        float2 v = *reinterpret_cast<const float2*>(q + (size_t)t * 2);
        g_qbf[t] = packbf(v.x, v.y);
    }
}

// ---------------- bf16 candidate GEMM: 128 rows x 64 cols per block, full K ----------------
#define GCOLS 64
#define BSTRIDE 132        // uint32 (bf16x2) per col: 128 data + 4 pad -> conflict-free frags

__global__ __launch_bounds__(256) void gemm_bf16_kernel(const float* __restrict__ key) {
    __shared__ uint32_t ksm[GCOLS * BSTRIDE];   // 33.8 KB
    const int tid = threadIdx.x;
    const int lane = tid & 31;
    const int warp = tid >> 5;
    const int cb = blockIdx.x * GCOLS;

    // load + convert B: 64 cols x 256 k fp32 -> bf16x2 (4096 float4)
#pragma unroll
    for (int it = 0; it < 16; it++) {
        int f4 = tid + it * 256;
        int col = f4 >> 6;          // 64 float4 per col
        int k4 = f4 & 63;
        float4 v = *reinterpret_cast<const float4*>(key + (size_t)(cb + col) * D + k4 * 4);
        ksm[col * BSTRIDE + k4 * 2]     = packbf(v.x, v.y);
        ksm[col * BSTRIDE + k4 * 2 + 1] = packbf(v.z, v.w);
    }
    __syncthreads();

    float acc[8][4];
#pragma unroll
    for (int j = 0; j < 8; j++)
#pragma unroll
        for (int e = 0; e < 4; e++) acc[j][e] = 0.0f;

    const int r0 = warp * 16 + (lane >> 2);   // A row for regs 0,2
    const int cc = lane & 3;                  // k-pair group

#pragma unroll
    for (int step = 0; step < 16; step++) {   // K = 256 = 16 * k16
        uint32_t a[4];
        a[0] = g_qbf[r0 * 128 + step * 8 + cc];
        a[1] = g_qbf[(r0 + 8) * 128 + step * 8 + cc];
        a[2] = g_qbf[r0 * 128 + step * 8 + 4 + cc];
        a[3] = g_qbf[(r0 + 8) * 128 + step * 8 + 4 + cc];
#pragma unroll
        for (int j = 0; j < 8; j++) {
            const uint32_t* bp = &ksm[(j * 8 + (lane >> 2)) * BSTRIDE + step * 8 + cc];
            mma_bf16(acc[j], a, bp[0], bp[4]);
        }
    }

    const int orow = warp * 16 + (lane >> 2);
    const int ocol = cb + (lane & 3) * 2;
#pragma unroll
    for (int j = 0; j < 8; j++) {
        g_logits[(size_t)orow * M + ocol + j * 8]           = acc[j][0];
        g_logits[(size_t)orow * M + ocol + j * 8 + 1]       = acc[j][1];
        g_logits[(size_t)(orow + 8) * M + ocol + j * 8]     = acc[j][2];
        g_logits[(size_t)(orow + 8) * M + ocol + j * 8 + 1] = acc[j][3];
    }
}

// ---------------- per-(row,chunk) top-24 candidates from bf16 scores ----------------
__device__ __forceinline__ unsigned long long desc_key(float v, int idx) {
    uint32_t u = __float_as_uint(v);
    uint32_t mono = (u & 0x80000000u) ? ~u : (u | 0x80000000u);  // ascending order
    uint32_t ord = ~mono;                                        // descending
    return ((unsigned long long)ord << 32) | (uint32_t)idx;
}

__global__ __launch_bounds__(256) void cand_kernel() {
    const int bid = blockIdx.x;          // 512 blocks
    const int row = bid >> 2;
    const int chunk = bid & 3;
    const int tid = threadIdx.x;

    unsigned long long lv[CAND_K];
#pragma unroll
    for (int j = 0; j < CAND_K; j++) lv[j] = 0xFFFFFFFFFFFFFFFFull;

    const float* lp = g_logits + (size_t)row * M + chunk * CHUNK;
    for (int m = tid; m < CHUNK; m += 256) {
        unsigned long long k = desc_key(lp[m], chunk * CHUNK + m);
        if (k < lv[CAND_K - 1]) {
            unsigned long long c = k;
#pragma unroll
            for (int j = 0; j < CAND_K; j++) {
                if (c < lv[j]) { unsigned long long t = lv[j]; lv[j] = c; c = t; }
            }
        }
    }

    __shared__ unsigned long long sk[256 * CAND_K];   // 48 KB
#pragma unroll
    for (int j = 0; j < CAND_K; j++) sk[tid * CAND_K + j] = lv[j];
    __syncthreads();

    for (int s = 128; s >= 1; s >>= 1) {
        if (tid < s) {
            const unsigned long long* a = &sk[tid * CAND_K];
            const unsigned long long* b = &sk[(tid + s) * CAND_K];
            unsigned long long o[CAND_K];
            int p = 0, qq = 0;
#pragma unroll
            for (int j = 0; j < CAND_K; j++) {
                bool ta;
                if (p >= CAND_K)       ta = false;
                else if (qq >= CAND_K) ta = true;
                else                   ta = (a[p] < b[qq]);
                if (ta) { o[j] = a[p]; p++; }
                else    { o[j] = b[qq]; qq++; }
            }
#pragma unroll
            for (int j = 0; j < CAND_K; j++) sk[tid * CAND_K + j] = o[j];
        }
        __syncthreads();
    }

    if (tid < CAND_K)
        g_cand_idx[row * NCAND + chunk * CAND_K + tid] = (int)(sk[tid] & 0xFFFFFFFFu);
}

// ---------------- exact fp32 rescore of 96 candidates + exact top-16 ----------------
__global__ __launch_bounds__(512) void rescore_kernel(const float* __restrict__ q,
                                                      const float* __restrict__ key) {
    const int row = blockIdx.x;
    const int tid = threadIdx.x;
    const int warp = tid >> 5;
    const int lane = tid & 31;

    __shared__ float sval[NCAND];
    __shared__ int   sidx[NCAND];

    float qv[8];
#pragma unroll
    for (int u = 0; u < 8; u++) qv[u] = q[(size_t)row * D + lane + 32 * u];

    for (int c = warp; c < NCAND; c += 16) {
        int idx = g_cand_idx[row * NCAND + c];
        const float* kp = key + (size_t)idx * D;
        float s = 0.0f;
#pragma unroll
        for (int u = 0; u < 8; u++) s = fmaf(qv[u], kp[lane + 32 * u], s);
#pragma unroll
        for (int o = 16; o; o >>= 1) s += __shfl_xor_sync(0xFFFFFFFFu, s, o);
        if (lane == 0) { sval[c] = s; sidx[c] = idx; }
    }
    __syncthreads();

    if (tid == 0) {
        float lv[NUM_TOP]; int li[NUM_TOP];
#pragma unroll
        for (int j = 0; j < NUM_TOP; j++) { lv[j] = -INFINITY; li[j] = 0x7FFFFFFF; }
        for (int c = 0; c < NCAND; c++) {
            float v = sval[c]; int idx = sidx[c];
            bool better_last = (v > lv[NUM_TOP - 1]) ||
                               (v == lv[NUM_TOP - 1] && idx < li[NUM_TOP - 1]);
            if (better_last) {
                float cv = v; int ci = idx;
#pragma unroll
                for (int j = 0; j < NUM_TOP; j++) {
                    if (cv > lv[j] || (cv == lv[j] && ci < li[j])) {
                        float tv = lv[j]; lv[j] = cv; cv = tv;
                        int ti = li[j]; li[j] = ci; ci = ti;
                    }
                }
            }
        }
#pragma unroll
        for (int j = 0; j < NUM_TOP; j++) {
            g_top_val[row * NUM_TOP + j] = lv[j];
            g_top_idx[row * NUM_TOP + j] = li[j];
        }
    }
}

// ---------------- exclusion mask ----------------
__global__ void zero_excl_kernel() {
    int i = blockIdx.x * 256 + threadIdx.x;
    if (i < M) g_excluded[i] = 0;
}

__global__ void scatter_excl_kernel() {
    int t = blockIdx.x * 256 + threadIdx.x;   // 2048 total
    if (t < R * NUM_TOP) g_excluded[g_top_idx[t]] = 1;
}

// ---------------- threefry2x32, partitionable: bits = x0out ^ x1out ----------------
__device__ __forceinline__ uint32_t rotl32(uint32_t x, int r) { return (x << r) | (x >> (32 - r)); }

#define TF_GROUP(a,b,c,d) \
    x0 += x1; x1 = rotl32(x1, a); x1 ^= x0; \
    x0 += x1; x1 = rotl32(x1, b); x1 ^= x0; \
    x0 += x1; x1 = rotl32(x1, c); x1 ^= x0; \
    x0 += x1; x1 = rotl32(x1, d); x1 ^= x0;

__global__ __launch_bounds__(1024) void rand_part_kernel() {
    const int tid = threadIdx.x;
    const int base = blockIdx.x * (M / 8);   // 8192 per block
    const uint32_t ks0 = 0u, ks1 = 42u, ks2 = 0x1BD11BDAu ^ 42u;

    unsigned long long best[NUM_RAND];
#pragma unroll
    for (int j = 0; j < NUM_RAND; j++) best[j] = 0xFFFFFFFFFFFFFFFFull;

    for (int i = base + tid; i < base + M / 8; i += 1024) {
        uint32_t x0 = 0u + ks0;            // counts_hi = 0
        uint32_t x1 = (uint32_t)i + ks1;   // counts_lo = i
        TF_GROUP(13, 15, 26, 6);  x0 += ks1; x1 += ks2 + 1u;
        TF_GROUP(17, 29, 16, 24); x0 += ks2; x1 += ks0 + 2u;
        TF_GROUP(13, 15, 26, 6);  x0 += ks0; x1 += ks1 + 3u;
        TF_GROUP(17, 29, 16, 24); x0 += ks1; x1 += ks2 + 4u;
        TF_GROUP(13, 15, 26, 6);  x0 += ks2; x1 += ks0 + 5u;
        uint32_t bits = x0 ^ x1;           // partitionable <64-bit combine
        uint32_t fb = g_excluded[i] ? 0x7F800000u : ((bits >> 9) | 0x3F800000u);
        unsigned long long kv = ((unsigned long long)fb << 32) | (uint32_t)i;
        if (kv < best[NUM_RAND - 1]) {
            unsigned long long c = kv;
#pragma unroll
            for (int j = 0; j < NUM_RAND; j++) {
                if (c < best[j]) { unsigned long long t = best[j]; best[j] = c; c = t; }
            }
        }
    }

    __shared__ unsigned long long sk[1024 * NUM_RAND];
#pragma unroll
    for (int j = 0; j < NUM_RAND; j++) sk[tid * NUM_RAND + j] = best[j];
    __syncthreads();

    for (int s = 512; s >= 1; s >>= 1) {
        if (tid < s) {
            const unsigned long long* a = &sk[tid * NUM_RAND];
            const unsigned long long* b = &sk[(tid + s) * NUM_RAND];
            unsigned long long o[NUM_RAND];
            int p = 0, qq = 0;
#pragma unroll
            for (int j = 0; j < NUM_RAND; j++) {
                bool ta;
                if (p >= NUM_RAND)       ta = false;
                else if (qq >= NUM_RAND) ta = true;
                else                     ta = (a[p] < b[qq]);
                if (ta) { o[j] = a[p]; p++; }
                else    { o[j] = b[qq]; qq++; }
            }
#pragma unroll
            for (int j = 0; j < NUM_RAND; j++) sk[tid * NUM_RAND + j] = o[j];
        }
        __syncthreads();
    }

    if (tid < NUM_RAND) g_rand_part[blockIdx.x * NUM_RAND + tid] = sk[tid];
}

__global__ void rand_merge_kernel() {
    if (threadIdx.x == 0) {
        unsigned long long best[NUM_RAND];
#pragma unroll
        for (int j = 0; j < NUM_RAND; j++) best[j] = 0xFFFFFFFFFFFFFFFFull;
        for (int i = 0; i < 8 * NUM_RAND; i++) {
            unsigned long long c = g_rand_part[i];
            if (c < best[NUM_RAND - 1]) {
#pragma unroll
                for (int j = 0; j < NUM_RAND; j++) {
                    if (c < best[j]) { unsigned long long t = best[j]; best[j] = c; c = t; }
                }
            }
        }
#pragma unroll
        for (int j = 0; j < NUM_RAND; j++) g_rand_idx[j] = (int)(best[j] & 0xFFFFFFFFu);
    }
}

// ---------------- composite + softmax + output ----------------
__global__ __launch_bounds__(32) void final_kernel(const float* __restrict__ q,
                                                   const float* __restrict__ key,
                                                   float* __restrict__ out) {
    const int row = blockIdx.x;
    const int lane = threadIdx.x;
    __shared__ float rl[NUM_RAND];

    const float* qp = q + (size_t)row * D;
#pragma unroll
    for (int j = 0; j < NUM_RAND; j++) {
        int idx = g_rand_idx[j];
        const float* kp = key + (size_t)idx * D;
        float s = 0.0f;
        for (int d = lane; d < D; d += 32) s = fmaf(qp[d], kp[d], s);
#pragma unroll
        for (int o = 16; o; o >>= 1) s += __shfl_xor_sync(0xFFFFFFFFu, s, o);
        if (lane == 0) rl[j] = s;
    }
    __syncwarp();

    if (lane == 0) {
        const int NC = NUM_TOP + NUM_RAND;  // 20
        float cl[NC]; int ci[NC];
#pragma unroll
        for (int j = 0; j < NUM_TOP; j++) {
            cl[j] = g_top_val[row * NUM_TOP + j];
            ci[j] = g_top_idx[row * NUM_TOP + j];
        }
#pragma unroll
        for (int j = 0; j < NUM_RAND; j++) {
            cl[NUM_TOP + j] = rl[j];
            ci[NUM_TOP + j] = g_rand_idx[j];
        }
        float mx = cl[0];
#pragma unroll
        for (int j = 1; j < NC; j++) mx = fmaxf(mx, cl[j]);
        float e[NC]; float sum = 0.0f;
#pragma unroll
        for (int j = 0; j < NC; j++) { e[j] = expf(cl[j] - mx); sum += e[j]; }
        float inv = 1.0f / sum;
#pragma unroll
        for (int j = 0; j < NC; j++) {
            out[row * NC + j] = (float)ci[j];                 // composite_idx (as f32)
            out[R * NC + row * NC + j] = e[j] * inv;          // composite_probs
        }
    }
}

// ---------------- launcher ----------------
extern "C" void kernel_launch(void* const* d_in, const int* in_sizes, int n_in,
                              void* d_out, int out_size) {
    const float* q   = (const float*)d_in[0];   // (8,16,256)
    const float* key = (const float*)d_in[1];   // (65536,256)
    float* out = (float*)d_out;

    zero_excl_kernel<<<M / 256, 256>>>();
    qconv_kernel<<<32, 512>>>(q);
    gemm_bf16_kernel<<<M / GCOLS, 256>>>(key);
    cand_kernel<<<R * NCHUNK, 256>>>();
    rescore_kernel<<<R, 512>>>(q, key);
    scatter_excl_kernel<<<(R * NUM_TOP + 255) / 256, 256>>>();
    rand_part_kernel<<<8, 1024>>>();
    rand_merge_kernel<<<1, 32>>>();
    final_kernel<<<R, 32>>>(q, key, out);
}

// round 7
// speedup vs baseline: 5.0973x; 2.3606x over previous
#include <cuda_runtime.h>
#include <math.h>
#include <stdint.h>

#define R 128        // B*H = 8*16
#define D 256        // head dim
#define M 65536      // memory slots
#define NUM_TOP 16
#define NUM_RAND 4
#define CAND_CAP 1024           // per-row candidate buffer cap

// ---------------- scratch (device globals; no allocations) ----------------
__device__ float g_logits[(size_t)R * M];       // 32 MB (bf16-accurate)
__device__ uint32_t g_qbf[R * (D / 2)];         // q as bf16x2 pairs, 64 KB
__device__ int   g_cand_idx[R * CAND_CAP];
__device__ int   g_cand_cnt[R];
__device__ float g_top_val[R * NUM_TOP];        // exact fp32 after rescore
__device__ int   g_top_idx[R * NUM_TOP];
__device__ int   g_excluded[M];
__device__ unsigned long long g_rand_part[8 * NUM_RAND];
__device__ int   g_rand_idx[NUM_RAND];

// ---------------- bf16 helpers ----------------
__device__ __forceinline__ uint32_t packbf(float lo, float hi) {
    uint32_t r;
    asm("cvt.rn.bf16x2.f32 %0, %1, %2;" : "=r"(r) : "f"(hi), "f"(lo));  // first src -> high half
    return r;
}

__device__ __forceinline__ void mma_bf16(float* c, const uint32_t* a, uint32_t b0, uint32_t b1) {
    asm volatile(
        "mma.sync.aligned.m16n8k16.row.col.f32.bf16.bf16.f32 "
        "{%0,%1,%2,%3}, {%4,%5,%6,%7}, {%8,%9}, {%0,%1,%2,%3};"
        : "+f"(c[0]), "+f"(c[1]), "+f"(c[2]), "+f"(c[3])
        : "r"(a[0]), "r"(a[1]), "r"(a[2]), "r"(a[3]), "r"(b0), "r"(b1));
}

// ---------------- q -> bf16x2 pre-conversion ----------------
__global__ __launch_bounds__(512) void qconv_kernel(const float* __restrict__ q) {
    int t = blockIdx.x * 512 + threadIdx.x;
    if (t < R * (D / 2)) {
        float2 v = *reinterpret_cast<const float2*>(q + (size_t)t * 2);
        g_qbf[t] = packbf(v.x, v.y);
    }
}

// ---------------- bf16 candidate GEMM: 128 rows x 64 cols per block, full K ----------------
#define GCOLS 64
#define BSTRIDE 132        // uint32 (bf16x2) per col: 128 data + 4 pad

__global__ __launch_bounds__(256) void gemm_bf16_kernel(const float* __restrict__ key) {
    __shared__ uint32_t ksm[GCOLS * BSTRIDE];   // 33.8 KB
    const int tid = threadIdx.x;
    const int lane = tid & 31;
    const int warp = tid >> 5;
    const int cb = blockIdx.x * GCOLS;

#pragma unroll
    for (int it = 0; it < 16; it++) {
        int f4 = tid + it * 256;
        int col = f4 >> 6;
        int k4 = f4 & 63;
        float4 v = *reinterpret_cast<const float4*>(key + (size_t)(cb + col) * D + k4 * 4);
        ksm[col * BSTRIDE + k4 * 2]     = packbf(v.x, v.y);
        ksm[col * BSTRIDE + k4 * 2 + 1] = packbf(v.z, v.w);
    }
    __syncthreads();

    float acc[8][4];
#pragma unroll
    for (int j = 0; j < 8; j++)
#pragma unroll
        for (int e = 0; e < 4; e++) acc[j][e] = 0.0f;

    const int r0 = warp * 16 + (lane >> 2);
    const int cc = lane & 3;

#pragma unroll
    for (int step = 0; step < 16; step++) {   // K = 256 = 16 * k16
        uint32_t a[4];
        a[0] = g_qbf[r0 * 128 + step * 8 + cc];
        a[1] = g_qbf[(r0 + 8) * 128 + step * 8 + cc];
        a[2] = g_qbf[r0 * 128 + step * 8 + 4 + cc];
        a[3] = g_qbf[(r0 + 8) * 128 + step * 8 + 4 + cc];
#pragma unroll
        for (int j = 0; j < 8; j++) {
            const uint32_t* bp = &ksm[(j * 8 + (lane >> 2)) * BSTRIDE + step * 8 + cc];
            mma_bf16(acc[j], a, bp[0], bp[4]);
        }
    }

    const int orow = warp * 16 + (lane >> 2);
    const int ocol = cb + (lane & 3) * 2;
#pragma unroll
    for (int j = 0; j < 8; j++) {
        g_logits[(size_t)orow * M + ocol + j * 8]           = acc[j][0];
        g_logits[(size_t)orow * M + ocol + j * 8 + 1]       = acc[j][1];
        g_logits[(size_t)(orow + 8) * M + ocol + j * 8]     = acc[j][2];
        g_logits[(size_t)(orow + 8) * M + ocol + j * 8 + 1] = acc[j][3];
    }
}

// ---------------- threshold-filter candidate selection: one block per row ----------------
__device__ __forceinline__ uint32_t mono_of(float f) {
    uint32_t u = __float_as_uint(f);
    return (u & 0x80000000u) ? ~u : (u | 0x80000000u);   // ascending monotone
}
__device__ __forceinline__ float float_of_mono(uint32_t m) {
    uint32_t u = (m & 0x80000000u) ? (m ^ 0x80000000u) : ~m;
    return __uint_as_float(u);
}

__global__ __launch_bounds__(1024) void cand_kernel() {
    const int row = blockIdx.x;
    const int tid = threadIdx.x;
    const float* lp = g_logits + (size_t)row * M;

    // pass 1: per-thread max over 64-float slice (16 float4, coalesced)
    float mx = -INFINITY;
#pragma unroll
    for (int it = 0; it < 16; it++) {
        float4 v = *reinterpret_cast<const float4*>(lp + (size_t)(tid + it * 1024) * 4);
        mx = fmaxf(mx, fmaxf(fmaxf(v.x, v.y), fmaxf(v.z, v.w)));
    }
    uint32_t mymono = mono_of(mx);

    // ballot-bisect: largest T_mono with count(slice_max > T) >= 16
    uint32_t lo = 0u, hi = 0xFFFFFFFFu;
    for (int it = 0; it < 32; it++) {
        uint32_t mid = lo + ((hi - lo) >> 1);
        int cnt = __syncthreads_count(mymono > mid);
        if (cnt >= NUM_TOP) lo = mid; else hi = mid;
    }
    // >=16 elements exceed float_of_mono(lo) => true 16th-largest > that value.
    // subtract margin >> bf16-vs-fp32 logit error so exact-fp32 top-16 is covered.
    const float thr = float_of_mono(lo) - 1.0f;

    __shared__ int s_cnt;
    if (tid == 0) s_cnt = 0;
    __syncthreads();

    // pass 2: compact indices above threshold (L2-resident re-read)
#pragma unroll
    for (int it = 0; it < 16; it++) {
        int f4 = tid + it * 1024;
        float4 v = *reinterpret_cast<const float4*>(lp + (size_t)f4 * 4);
        int base = f4 * 4;
#pragma unroll
        for (int e = 0; e < 4; e++) {
            float val = (e == 0) ? v.x : (e == 1) ? v.y : (e == 2) ? v.z : v.w;
            if (val > thr) {
                int pos = atomicAdd(&s_cnt, 1);
                if (pos < CAND_CAP) g_cand_idx[row * CAND_CAP + pos] = base + e;
            }
        }
    }
    __syncthreads();
    if (tid == 0) g_cand_cnt[row] = (s_cnt < CAND_CAP) ? s_cnt : CAND_CAP;
}

// ---------------- exact fp32 rescore of candidates + exact top-16 ----------------
__global__ __launch_bounds__(512) void rescore_kernel(const float* __restrict__ q,
                                                      const float* __restrict__ key) {
    const int row = blockIdx.x;
    const int tid = threadIdx.x;
    const int warp = tid >> 5;
    const int lane = tid & 31;

    __shared__ float sval[CAND_CAP];
    __shared__ int   sidx[CAND_CAP];

    const int cnt = g_cand_cnt[row];

    float qv[8];
#pragma unroll
    for (int u = 0; u < 8; u++) qv[u] = q[(size_t)row * D + lane + 32 * u];

    for (int c = warp; c < cnt; c += 16) {
        int idx = g_cand_idx[row * CAND_CAP + c];
        const float* kp = key + (size_t)idx * D;
        float s = 0.0f;
#pragma unroll
        for (int u = 0; u < 8; u++) s = fmaf(qv[u], kp[lane + 32 * u], s);
#pragma unroll
        for (int o = 16; o; o >>= 1) s += __shfl_xor_sync(0xFFFFFFFFu, s, o);
        if (lane == 0) { sval[c] = s; sidx[c] = idx; }
    }
    __syncthreads();

    if (tid == 0) {
        float lv[NUM_TOP]; int li[NUM_TOP];
#pragma unroll
        for (int j = 0; j < NUM_TOP; j++) { lv[j] = -INFINITY; li[j] = 0x7FFFFFFF; }
        for (int c = 0; c < cnt; c++) {
            float v = sval[c]; int idx = sidx[c];
            bool better_last = (v > lv[NUM_TOP - 1]) ||
                               (v == lv[NUM_TOP - 1] && idx < li[NUM_TOP - 1]);
            if (better_last) {
                float cv = v; int ci = idx;
#pragma unroll
                for (int j = 0; j < NUM_TOP; j++) {
                    if (cv > lv[j] || (cv == lv[j] && ci < li[j])) {
                        float tv = lv[j]; lv[j] = cv; cv = tv;
                        int ti = li[j]; li[j] = ci; ci = ti;
                    }
                }
            }
        }
#pragma unroll
        for (int j = 0; j < NUM_TOP; j++) {
            g_top_val[row * NUM_TOP + j] = lv[j];
            g_top_idx[row * NUM_TOP + j] = li[j];
        }
    }
}

// ---------------- exclusion mask ----------------
__global__ void zero_excl_kernel() {
    int i = blockIdx.x * 256 + threadIdx.x;
    if (i < M) g_excluded[i] = 0;
}

__global__ void scatter_excl_kernel() {
    int t = blockIdx.x * 256 + threadIdx.x;   // 2048 total
    if (t < R * NUM_TOP) g_excluded[g_top_idx[t]] = 1;
}

// ---------------- threefry2x32, partitionable: bits = x0out ^ x1out ----------------
__device__ __forceinline__ uint32_t rotl32(uint32_t x, int r) { return (x << r) | (x >> (32 - r)); }

#define TF_GROUP(a,b,c,d) \
    x0 += x1; x1 = rotl32(x1, a); x1 ^= x0; \
    x0 += x1; x1 = rotl32(x1, b); x1 ^= x0; \
    x0 += x1; x1 = rotl32(x1, c); x1 ^= x0; \
    x0 += x1; x1 = rotl32(x1, d); x1 ^= x0;

__global__ __launch_bounds__(1024) void rand_part_kernel() {
    const int tid = threadIdx.x;
    const int base = blockIdx.x * (M / 8);
    const uint32_t ks0 = 0u, ks1 = 42u, ks2 = 0x1BD11BDAu ^ 42u;

    unsigned long long best[NUM_RAND];
#pragma unroll
    for (int j = 0; j < NUM_RAND; j++) best[j] = 0xFFFFFFFFFFFFFFFFull;

    for (int i = base + tid; i < base + M / 8; i += 1024) {
        uint32_t x0 = 0u + ks0;            // counts_hi = 0
        uint32_t x1 = (uint32_t)i + ks1;   // counts_lo = i
        TF_GROUP(13, 15, 26, 6);  x0 += ks1; x1 += ks2 + 1u;
        TF_GROUP(17, 29, 16, 24); x0 += ks2; x1 += ks0 + 2u;
        TF_GROUP(13, 15, 26, 6);  x0 += ks0; x1 += ks1 + 3u;
        TF_GROUP(17, 29, 16, 24); x0 += ks1; x1 += ks2 + 4u;
        TF_GROUP(13, 15, 26, 6);  x0 += ks2; x1 += ks0 + 5u;
        uint32_t bits = x0 ^ x1;           // partitionable <64-bit combine
        uint32_t fb = g_excluded[i] ? 0x7F800000u : ((bits >> 9) | 0x3F800000u);
        unsigned long long kv = ((unsigned long long)fb << 32) | (uint32_t)i;
        if (kv < best[NUM_RAND - 1]) {
            unsigned long long c = kv;
#pragma unroll
            for (int j = 0; j < NUM_RAND; j++) {
                if (c < best[j]) { unsigned long long t = best[j]; best[j] = c; c = t; }
            }
        }
    }

    __shared__ unsigned long long sk[1024 * NUM_RAND];
#pragma unroll
    for (int j = 0; j < NUM_RAND; j++) sk[tid * NUM_RAND + j] = best[j];
    __syncthreads();

    for (int s = 512; s >= 1; s >>= 1) {
        if (tid < s) {
            const unsigned long long* a = &sk[tid * NUM_RAND];
            const unsigned long long* b = &sk[(tid + s) * NUM_RAND];
            unsigned long long o[NUM_RAND];
            int p = 0, qq = 0;
#pragma unroll
            for (int j = 0; j < NUM_RAND; j++) {
                bool ta;
                if (p >= NUM_RAND)       ta = false;
                else if (qq >= NUM_RAND) ta = true;
                else                     ta = (a[p] < b[qq]);
                if (ta) { o[j] = a[p]; p++; }
                else    { o[j] = b[qq]; qq++; }
            }
#pragma unroll
            for (int j = 0; j < NUM_RAND; j++) sk[tid * NUM_RAND + j] = o[j];
        }
        __syncthreads();
    }

    if (tid < NUM_RAND) g_rand_part[blockIdx.x * NUM_RAND + tid] = sk[tid];
}

__global__ void rand_merge_kernel() {
    if (threadIdx.x == 0) {
        unsigned long long best[NUM_RAND];
#pragma unroll
        for (int j = 0; j < NUM_RAND; j++) best[j] = 0xFFFFFFFFFFFFFFFFull;
        for (int i = 0; i < 8 * NUM_RAND; i++) {
            unsigned long long c = g_rand_part[i];
            if (c < best[NUM_RAND - 1]) {
#pragma unroll
                for (int j = 0; j < NUM_RAND; j++) {
                    if (c < best[j]) { unsigned long long t = best[j]; best[j] = c; c = t; }
                }
            }
        }
#pragma unroll
        for (int j = 0; j < NUM_RAND; j++) g_rand_idx[j] = (int)(best[j] & 0xFFFFFFFFu);
    }
}

// ---------------- composite + softmax + output ----------------
__global__ __launch_bounds__(32) void final_kernel(const float* __restrict__ q,
                                                   const float* __restrict__ key,
                                                   float* __restrict__ out) {
    const int row = blockIdx.x;
    const int lane = threadIdx.x;
    __shared__ float rl[NUM_RAND];

    const float* qp = q + (size_t)row * D;
#pragma unroll
    for (int j = 0; j < NUM_RAND; j++) {
        int idx = g_rand_idx[j];
        const float* kp = key + (size_t)idx * D;
        float s = 0.0f;
        for (int d = lane; d < D; d += 32) s = fmaf(qp[d], kp[d], s);
#pragma unroll
        for (int o = 16; o; o >>= 1) s += __shfl_xor_sync(0xFFFFFFFFu, s, o);
        if (lane == 0) rl[j] = s;
    }
    __syncwarp();

    if (lane == 0) {
        const int NC = NUM_TOP + NUM_RAND;  // 20
        float cl[NC]; int ci[NC];
#pragma unroll
        for (int j = 0; j < NUM_TOP; j++) {
            cl[j] = g_top_val[row * NUM_TOP + j];
            ci[j] = g_top_idx[row * NUM_TOP + j];
        }
#pragma unroll
        for (int j = 0; j < NUM_RAND; j++) {
            cl[NUM_TOP + j] = rl[j];
            ci[NUM_TOP + j] = g_rand_idx[j];
        }
        float mx = cl[0];
#pragma unroll
        for (int j = 1; j < NC; j++) mx = fmaxf(mx, cl[j]);
        float e[NC]; float sum = 0.0f;
#pragma unroll
        for (int j = 0; j < NC; j++) { e[j] = expf(cl[j] - mx); sum += e[j]; }
        float inv = 1.0f / sum;
#pragma unroll
        for (int j = 0; j < NC; j++) {
            out[row * NC + j] = (float)ci[j];                 // composite_idx (as f32)
            out[R * NC + row * NC + j] = e[j] * inv;          // composite_probs
        }
    }
}

// ---------------- launcher ----------------
extern "C" void kernel_launch(void* const* d_in, const int* in_sizes, int n_in,
                              void* d_out, int out_size) {
    const float* q   = (const float*)d_in[0];   // (8,16,256)
    const float* key = (const float*)d_in[1];   // (65536,256)
    float* out = (float*)d_out;

    zero_excl_kernel<<<M / 256, 256>>>();
    qconv_kernel<<<32, 512>>>(q);
    gemm_bf16_kernel<<<M / GCOLS, 256>>>(key);
    cand_kernel<<<R, 1024>>>();
    rescore_kernel<<<R, 512>>>(q, key);
    scatter_excl_kernel<<<(R * NUM_TOP + 255) / 256, 256>>>();
    rand_part_kernel<<<8, 1024>>>();
    rand_merge_kernel<<<1, 32>>>();
    final_kernel<<<R, 32>>>(q, key, out);
}

// round 8
// speedup vs baseline: 5.7830x; 1.1345x over previous
#include <cuda_runtime.h>
#include <cuda_bf16.h>
#include <math.h>
#include <stdint.h>

#define R 128        // B*H = 8*16
#define D 256        // head dim
#define M 65536      // memory slots
#define NUM_TOP 16
#define NUM_RAND 4
#define CAND_CAP 1024           // per-row candidate buffer cap
#define RAND_BLOCKS 32

// ---------------- scratch (device globals; no allocations) ----------------
__device__ uint32_t g_logits_bf[(size_t)R * M / 2];  // 16 MB, bf16x2 packed
__device__ uint32_t g_qbf[R * (D / 2)];              // q as bf16x2 pairs, 64 KB
__device__ int   g_cand_idx[R * CAND_CAP];
__device__ int   g_cand_cnt[R];
__device__ float g_top_val[R * NUM_TOP];             // exact fp32 after rescore
__device__ int   g_top_idx[R * NUM_TOP];
__device__ int   g_excluded[M];
__device__ unsigned long long g_rand_part[RAND_BLOCKS * NUM_RAND];

// ---------------- bf16 helpers ----------------
__device__ __forceinline__ uint32_t packbf(float lo, float hi) {
    uint32_t r;
    asm("cvt.rn.bf16x2.f32 %0, %1, %2;" : "=r"(r) : "f"(hi), "f"(lo));  // first src -> high half
    return r;
}

__device__ __forceinline__ void mma_bf16(float* c, const uint32_t* a, uint32_t b0, uint32_t b1) {
    asm volatile(
        "mma.sync.aligned.m16n8k16.row.col.f32.bf16.bf16.f32 "
        "{%0,%1,%2,%3}, {%4,%5,%6,%7}, {%8,%9}, {%0,%1,%2,%3};"
        : "+f"(c[0]), "+f"(c[1]), "+f"(c[2]), "+f"(c[3])
        : "r"(a[0]), "r"(a[1]), "r"(a[2]), "r"(a[3]), "r"(b0), "r"(b1));
}

// ---------------- init: zero exclusion mask + q -> bf16x2 ----------------
__global__ __launch_bounds__(256) void init_kernel(const float* __restrict__ q) {
    int t = blockIdx.x * 256 + threadIdx.x;   // 256 blocks x 256 = 65536
    if (t < M) g_excluded[t] = 0;
    if (t < R * (D / 2)) {
        float2 v = *reinterpret_cast<const float2*>(q + (size_t)t * 2);
        g_qbf[t] = packbf(v.x, v.y);
    }
}

// ---------------- bf16 candidate GEMM: 128 rows x 64 cols per block, full K ----------------
#define GCOLS 64
#define BSTRIDE 132        // uint32 (bf16x2) per col: 128 data + 4 pad

__global__ __launch_bounds__(256) void gemm_bf16_kernel(const float* __restrict__ key) {
    __shared__ uint32_t ksm[GCOLS * BSTRIDE];   // 33.8 KB
    const int tid = threadIdx.x;
    const int lane = tid & 31;
    const int warp = tid >> 5;
    const int cb = blockIdx.x * GCOLS;

#pragma unroll
    for (int it = 0; it < 16; it++) {
        int f4 = tid + it * 256;
        int col = f4 >> 6;
        int k4 = f4 & 63;
        float4 v = *reinterpret_cast<const float4*>(key + (size_t)(cb + col) * D + k4 * 4);
        ksm[col * BSTRIDE + k4 * 2]     = packbf(v.x, v.y);
        ksm[col * BSTRIDE + k4 * 2 + 1] = packbf(v.z, v.w);
    }
    __syncthreads();

    float acc[8][4];
#pragma unroll
    for (int j = 0; j < 8; j++)
#pragma unroll
        for (int e = 0; e < 4; e++) acc[j][e] = 0.0f;

    const int r0 = warp * 16 + (lane >> 2);
    const int cc = lane & 3;

#pragma unroll
    for (int step = 0; step < 16; step++) {   // K = 256 = 16 * k16
        uint32_t a[4];
        a[0] = g_qbf[r0 * 128 + step * 8 + cc];
        a[1] = g_qbf[(r0 + 8) * 128 + step * 8 + cc];
        a[2] = g_qbf[r0 * 128 + step * 8 + 4 + cc];
        a[3] = g_qbf[(r0 + 8) * 128 + step * 8 + 4 + cc];
#pragma unroll
        for (int j = 0; j < 8; j++) {
            const uint32_t* bp = &ksm[(j * 8 + (lane >> 2)) * BSTRIDE + step * 8 + cc];
            mma_bf16(acc[j], a, bp[0], bp[4]);
        }
    }

    // acc[j][0]/acc[j][1] are adjacent cols -> pack to one bf16x2 word
    const int orow = warp * 16 + (lane >> 2);
    const int ocol = cb + (lane & 3) * 2;
#pragma unroll
    for (int j = 0; j < 8; j++) {
        g_logits_bf[((size_t)orow * M + ocol + j * 8) >> 1]       = packbf(acc[j][0], acc[j][1]);
        g_logits_bf[((size_t)(orow + 8) * M + ocol + j * 8) >> 1] = packbf(acc[j][2], acc[j][3]);
    }
}

// ---------------- threshold-filter candidate selection: one block per row ----------------
__device__ __forceinline__ uint32_t mono_of(float f) {
    uint32_t u = __float_as_uint(f);
    return (u & 0x80000000u) ? ~u : (u | 0x80000000u);   // ascending monotone
}
__device__ __forceinline__ float float_of_mono(uint32_t m) {
    uint32_t u = (m & 0x80000000u) ? (m ^ 0x80000000u) : ~m;
    return __uint_as_float(u);
}

__global__ __launch_bounds__(1024) void cand_kernel() {
    const int row = blockIdx.x;
    const int tid = threadIdx.x;
    const uint32_t* lp = g_logits_bf + (size_t)row * (M / 2);   // 32768 u32

    // pass 1: per-thread max over 64 bf16 (8 uint4 = 32 u32)
    float mx = -INFINITY;
#pragma unroll
    for (int it = 0; it < 8; it++) {
        uint4 v = *reinterpret_cast<const uint4*>(lp + (size_t)(tid + it * 1024) * 4);
#pragma unroll
        for (int w = 0; w < 4; w++) {
            uint32_t pw = (w == 0) ? v.x : (w == 1) ? v.y : (w == 2) ? v.z : v.w;
            float2 f = __bfloat1622float2(*reinterpret_cast<__nv_bfloat162*>(&pw));
            mx = fmaxf(mx, fmaxf(f.x, f.y));
        }
    }
    uint32_t mymono = mono_of(mx);

    // ballot-bisect: largest T_mono with count(slice_max > T) >= 16
    uint32_t lo = 0u, hi = 0xFFFFFFFFu;
    for (int it = 0; it < 32; it++) {
        uint32_t mid = lo + ((hi - lo) >> 1);
        int cnt = __syncthreads_count(mymono > mid);
        if (cnt >= NUM_TOP) lo = mid; else hi = mid;
    }
    // true (stored) 16th-largest > float_of_mono(lo); margin covers bf16 gemm +
    // bf16 storage error on both sides (~0.45+0.45 < 1.5)
    const float thr = float_of_mono(lo) - 1.5f;

    __shared__ int s_cnt;
    if (tid == 0) s_cnt = 0;
    __syncthreads();

    // pass 2: compact indices above threshold (L2-resident re-read)
#pragma unroll
    for (int it = 0; it < 8; it++) {
        int f4 = tid + it * 1024;
        uint4 v = *reinterpret_cast<const uint4*>(lp + (size_t)f4 * 4);
        int base = f4 * 8;
#pragma unroll
        for (int w = 0; w < 4; w++) {
            uint32_t pw = (w == 0) ? v.x : (w == 1) ? v.y : (w == 2) ? v.z : v.w;
            float2 f = __bfloat1622float2(*reinterpret_cast<__nv_bfloat162*>(&pw));
            if (f.x > thr) {
                int pos = atomicAdd(&s_cnt, 1);
                if (pos < CAND_CAP) g_cand_idx[row * CAND_CAP + pos] = base + w * 2;
            }
            if (f.y > thr) {
                int pos = atomicAdd(&s_cnt, 1);
                if (pos < CAND_CAP) g_cand_idx[row * CAND_CAP + pos] = base + w * 2 + 1;
            }
        }
    }
    __syncthreads();
    if (tid == 0) g_cand_cnt[row] = (s_cnt < CAND_CAP) ? s_cnt : CAND_CAP;
}

// ---------------- exact fp32 rescore + exact top-16 + exclusion scatter ----------------
__global__ __launch_bounds__(512) void rescore_kernel(const float* __restrict__ q,
                                                      const float* __restrict__ key) {
    const int row = blockIdx.x;
    const int tid = threadIdx.x;
    const int warp = tid >> 5;
    const int lane = tid & 31;

    __shared__ float sval[CAND_CAP];
    __shared__ int   sidx[CAND_CAP];

    const int cnt = g_cand_cnt[row];

    float qv[8];
#pragma unroll
    for (int u = 0; u < 8; u++) qv[u] = q[(size_t)row * D + lane + 32 * u];

    for (int c = warp; c < cnt; c += 16) {
        int idx = g_cand_idx[row * CAND_CAP + c];
        const float* kp = key + (size_t)idx * D;
        float s = 0.0f;
#pragma unroll
        for (int u = 0; u < 8; u++) s = fmaf(qv[u], kp[lane + 32 * u], s);
#pragma unroll
        for (int o = 16; o; o >>= 1) s += __shfl_xor_sync(0xFFFFFFFFu, s, o);
        if (lane == 0) { sval[c] = s; sidx[c] = idx; }
    }
    __syncthreads();

    if (tid == 0) {
        float lv[NUM_TOP]; int li[NUM_TOP];
#pragma unroll
        for (int j = 0; j < NUM_TOP; j++) { lv[j] = -INFINITY; li[j] = 0x7FFFFFFF; }
        for (int c = 0; c < cnt; c++) {
            float v = sval[c]; int idx = sidx[c];
            bool better_last = (v > lv[NUM_TOP - 1]) ||
                               (v == lv[NUM_TOP - 1] && idx < li[NUM_TOP - 1]);
            if (better_last) {
                float cv = v; int ci = idx;
#pragma unroll
                for (int j = 0; j < NUM_TOP; j++) {
                    if (cv > lv[j] || (cv == lv[j] && ci < li[j])) {
                        float tv = lv[j]; lv[j] = cv; cv = tv;
                        int ti = li[j]; li[j] = ci; ci = ti;
                    }
                }
            }
        }
#pragma unroll
        for (int j = 0; j < NUM_TOP; j++) {
            g_top_val[row * NUM_TOP + j] = lv[j];
            g_top_idx[row * NUM_TOP + j] = li[j];
            g_excluded[li[j]] = 1;               // fused exclusion scatter
        }
    }
}

// ---------------- threefry2x32, partitionable: bits = x0out ^ x1out ----------------
__device__ __forceinline__ uint32_t rotl32(uint32_t x, int r) { return (x << r) | (x >> (32 - r)); }

#define TF_GROUP(a,b,c,d) \
    x0 += x1; x1 = rotl32(x1, a); x1 ^= x0; \
    x0 += x1; x1 = rotl32(x1, b); x1 ^= x0; \
    x0 += x1; x1 = rotl32(x1, c); x1 ^= x0; \
    x0 += x1; x1 = rotl32(x1, d); x1 ^= x0;

__global__ __launch_bounds__(1024) void rand_part_kernel() {
    const int tid = threadIdx.x;
    const int base = blockIdx.x * (M / RAND_BLOCKS);   // 2048 per block
    const uint32_t ks0 = 0u, ks1 = 42u, ks2 = 0x1BD11BDAu ^ 42u;

    unsigned long long best[NUM_RAND];
#pragma unroll
    for (int j = 0; j < NUM_RAND; j++) best[j] = 0xFFFFFFFFFFFFFFFFull;

    for (int i = base + tid; i < base + M / RAND_BLOCKS; i += 1024) {
        uint32_t x0 = 0u + ks0;            // counts_hi = 0
        uint32_t x1 = (uint32_t)i + ks1;   // counts_lo = i
        TF_GROUP(13, 15, 26, 6);  x0 += ks1; x1 += ks2 + 1u;
        TF_GROUP(17, 29, 16, 24); x0 += ks2; x1 += ks0 + 2u;
        TF_GROUP(13, 15, 26, 6);  x0 += ks0; x1 += ks1 + 3u;
        TF_GROUP(17, 29, 16, 24); x0 += ks1; x1 += ks2 + 4u;
        TF_GROUP(13, 15, 26, 6);  x0 += ks2; x1 += ks0 + 5u;
        uint32_t bits = x0 ^ x1;           // partitionable <64-bit combine
        uint32_t fb = g_excluded[i] ? 0x7F800000u : ((bits >> 9) | 0x3F800000u);
        unsigned long long kv = ((unsigned long long)fb << 32) | (uint32_t)i;
        if (kv < best[NUM_RAND - 1]) {
            unsigned long long c = kv;
#pragma unroll
            for (int j = 0; j < NUM_RAND; j++) {
                if (c < best[j]) { unsigned long long t = best[j]; best[j] = c; c = t; }
            }
        }
    }

    __shared__ unsigned long long sk[1024 * NUM_RAND];
#pragma unroll
    for (int j = 0; j < NUM_RAND; j++) sk[tid * NUM_RAND + j] = best[j];
    __syncthreads();

    for (int s = 512; s >= 1; s >>= 1) {
        if (tid < s) {
            const unsigned long long* a = &sk[tid * NUM_RAND];
            const unsigned long long* b = &sk[(tid + s) * NUM_RAND];
            unsigned long long o[NUM_RAND];
            int p = 0, qq = 0;
#pragma unroll
            for (int j = 0; j < NUM_RAND; j++) {
                bool ta;
                if (p >= NUM_RAND)       ta = false;
                else if (qq >= NUM_RAND) ta = true;
                else                     ta = (a[p] < b[qq]);
                if (ta) { o[j] = a[p]; p++; }
                else    { o[j] = b[qq]; qq++; }
            }
#pragma unroll
            for (int j = 0; j < NUM_RAND; j++) sk[tid * NUM_RAND + j] = o[j];
        }
        __syncthreads();
    }

    if (tid < NUM_RAND) g_rand_part[blockIdx.x * NUM_RAND + tid] = sk[tid];
}

// ---------------- composite + softmax + output (rand merge fused) ----------------
__global__ __launch_bounds__(32) void final_kernel(const float* __restrict__ q,
                                                   const float* __restrict__ key,
                                                   float* __restrict__ out) {
    const int row = blockIdx.x;
    const int lane = threadIdx.x;
    __shared__ float rl[NUM_RAND];
    __shared__ int   ri[NUM_RAND];

    // every block deterministically merges the rand partials (128 u64, L2-hot)
    if (lane == 0) {
        unsigned long long best[NUM_RAND];
#pragma unroll
        for (int j = 0; j < NUM_RAND; j++) best[j] = 0xFFFFFFFFFFFFFFFFull;
        for (int i = 0; i < RAND_BLOCKS * NUM_RAND; i++) {
            unsigned long long c = g_rand_part[i];
            if (c < best[NUM_RAND - 1]) {
#pragma unroll
                for (int j = 0; j < NUM_RAND; j++) {
                    if (c < best[j]) { unsigned long long t = best[j]; best[j] = c; c = t; }
                }
            }
        }
#pragma unroll
        for (int j = 0; j < NUM_RAND; j++) ri[j] = (int)(best[j] & 0xFFFFFFFFu);
    }
    __syncwarp();

    const float* qp = q + (size_t)row * D;
#pragma unroll
    for (int j = 0; j < NUM_RAND; j++) {
        int idx = ri[j];
        const float* kp = key + (size_t)idx * D;
        float s = 0.0f;
        for (int d = lane; d < D; d += 32) s = fmaf(qp[d], kp[d], s);
#pragma unroll
        for (int o = 16; o; o >>= 1) s += __shfl_xor_sync(0xFFFFFFFFu, s, o);
        if (lane == 0) rl[j] = s;
    }
    __syncwarp();

    if (lane == 0) {
        const int NC = NUM_TOP + NUM_RAND;  // 20
        float cl[NC]; int ci[NC];
#pragma unroll
        for (int j = 0; j < NUM_TOP; j++) {
            cl[j] = g_top_val[row * NUM_TOP + j];
            ci[j] = g_top_idx[row * NUM_TOP + j];
        }
#pragma unroll
        for (int j = 0; j < NUM_RAND; j++) {
            cl[NUM_TOP + j] = rl[j];
            ci[NUM_TOP + j] = ri[j];
        }
        float mx = cl[0];
#pragma unroll
        for (int j = 1; j < NC; j++) mx = fmaxf(mx, cl[j]);
        float e[NC]; float sum = 0.0f;
#pragma unroll
        for (int j = 0; j < NC; j++) { e[j] = expf(cl[j] - mx); sum += e[j]; }
        float inv = 1.0f / sum;
#pragma unroll
        for (int j = 0; j < NC; j++) {
            out[row * NC + j] = (float)ci[j];                 // composite_idx (as f32)
            out[R * NC + row * NC + j] = e[j] * inv;          // composite_probs
        }
    }
}

// ---------------- launcher ----------------
extern "C" void kernel_launch(void* const* d_in, const int* in_sizes, int n_in,
                              void* d_out, int out_size) {
    const float* q   = (const float*)d_in[0];   // (8,16,256)
    const float* key = (const float*)d_in[1];   // (65536,256)
    float* out = (float*)d_out;

    init_kernel<<<256, 256>>>(q);
    gemm_bf16_kernel<<<M / GCOLS, 256>>>(key);
    cand_kernel<<<R, 1024>>>();
    rescore_kernel<<<R, 512>>>(q, key);
    rand_part_kernel<<<RAND_BLOCKS, 1024>>>();
    final_kernel<<<R, 32>>>(q, key, out);
}

// round 9
// speedup vs baseline: 6.0427x; 1.0449x over previous
#include <cuda_runtime.h>
#include <cuda_bf16.h>
#include <math.h>
#include <stdint.h>

#define R 128        // B*H = 8*16
#define D 256        // head dim
#define M 65536      // memory slots
#define NUM_TOP 16
#define NUM_RAND 4
#define CAND_CAP 1024           // per-row candidate buffer cap
#define RAND_BLOCKS 32

// ---------------- scratch (device globals; no allocations) ----------------
__device__ uint32_t g_logits_bf[(size_t)R * M / 2];  // 16 MB, bf16x2 packed
__device__ uint32_t g_qbf[R * (D / 2)];              // q as bf16x2 pairs, 64 KB
__device__ float g_top_val[R * NUM_TOP];             // exact fp32 after rescore
__device__ int   g_top_idx[R * NUM_TOP];
__device__ int   g_excluded[M];
__device__ unsigned long long g_rand_part[RAND_BLOCKS * NUM_RAND];

// ---------------- bf16 helpers ----------------
__device__ __forceinline__ uint32_t packbf(float lo, float hi) {
    uint32_t r;
    asm("cvt.rn.bf16x2.f32 %0, %1, %2;" : "=r"(r) : "f"(hi), "f"(lo));  // first src -> high half
    return r;
}

__device__ __forceinline__ void mma_bf16(float* c, const uint32_t* a, uint32_t b0, uint32_t b1) {
    asm volatile(
        "mma.sync.aligned.m16n8k16.row.col.f32.bf16.bf16.f32 "
        "{%0,%1,%2,%3}, {%4,%5,%6,%7}, {%8,%9}, {%0,%1,%2,%3};"
        : "+f"(c[0]), "+f"(c[1]), "+f"(c[2]), "+f"(c[3])
        : "r"(a[0]), "r"(a[1]), "r"(a[2]), "r"(a[3]), "r"(b0), "r"(b1));
}

// ---------------- init: zero exclusion mask + q -> bf16x2 ----------------
__global__ __launch_bounds__(256) void init_kernel(const float* __restrict__ q) {
    int t = blockIdx.x * 256 + threadIdx.x;   // 256 x 256 = 65536
    if (t < M) g_excluded[t] = 0;
    if (t < R * (D / 2)) {
        float2 v = *reinterpret_cast<const float2*>(q + (size_t)t * 2);
        g_qbf[t] = packbf(v.x, v.y);
    }
}

// ---------------- bf16 candidate GEMM: 128 rows x 64 cols per block, full K ----------------
#define GCOLS 64
#define BSTRIDE 132        // uint32 (bf16x2) per col: 128 data + 4 pad

__global__ __launch_bounds__(256) void gemm_bf16_kernel(const float* __restrict__ key) {
    __shared__ uint32_t ksm[GCOLS * BSTRIDE];   // 33.8 KB
    const int tid = threadIdx.x;
    const int lane = tid & 31;
    const int warp = tid >> 5;
    const int cb = blockIdx.x * GCOLS;

#pragma unroll
    for (int it = 0; it < 16; it++) {
        int f4 = tid + it * 256;
        int col = f4 >> 6;
        int k4 = f4 & 63;
        float4 v = *reinterpret_cast<const float4*>(key + (size_t)(cb + col) * D + k4 * 4);
        ksm[col * BSTRIDE + k4 * 2]     = packbf(v.x, v.y);
        ksm[col * BSTRIDE + k4 * 2 + 1] = packbf(v.z, v.w);
    }
    __syncthreads();

    float acc[8][4];
#pragma unroll
    for (int j = 0; j < 8; j++)
#pragma unroll
        for (int e = 0; e < 4; e++) acc[j][e] = 0.0f;

    const int r0 = warp * 16 + (lane >> 2);
    const int cc = lane & 3;

#pragma unroll
    for (int step = 0; step < 16; step++) {   // K = 256 = 16 * k16
        uint32_t a[4];
        a[0] = g_qbf[r0 * 128 + step * 8 + cc];
        a[1] = g_qbf[(r0 + 8) * 128 + step * 8 + cc];
        a[2] = g_qbf[r0 * 128 + step * 8 + 4 + cc];
        a[3] = g_qbf[(r0 + 8) * 128 + step * 8 + 4 + cc];
#pragma unroll
        for (int j = 0; j < 8; j++) {
            const uint32_t* bp = &ksm[(j * 8 + (lane >> 2)) * BSTRIDE + step * 8 + cc];
            mma_bf16(acc[j], a, bp[0], bp[4]);
        }
    }

    const int orow = warp * 16 + (lane >> 2);
    const int ocol = cb + (lane & 3) * 2;
#pragma unroll
    for (int j = 0; j < 8; j++) {
        g_logits_bf[((size_t)orow * M + ocol + j * 8) >> 1]       = packbf(acc[j][0], acc[j][1]);
        g_logits_bf[((size_t)(orow + 8) * M + ocol + j * 8) >> 1] = packbf(acc[j][2], acc[j][3]);
    }
}

// ---------------- bf16-mono helpers (16-bit order-preserving) ----------------
__device__ __forceinline__ uint32_t mono16_of(float f) {
    // f is exactly representable in bf16 here
    uint16_t h = (uint16_t)(__float_as_uint(f) >> 16);
    return (h & 0x8000u) ? (uint32_t)((uint16_t)~h) : (uint32_t)(h | 0x8000u);
}
__device__ __forceinline__ float float_of_mono16(uint32_t m) {
    uint16_t h = (m & 0x8000u) ? (uint16_t)(m ^ 0x8000u) : (uint16_t)(~m & 0xFFFFu);
    return __uint_as_float(((uint32_t)h) << 16);
}

// ---------------- fused: threshold-filter + exact fp32 rescore + top-16 + exclusion ----------------
__global__ __launch_bounds__(1024) void candrescore_kernel(const float* __restrict__ q,
                                                           const float* __restrict__ key) {
    const int row = blockIdx.x;
    const int tid = threadIdx.x;
    const int warp = tid >> 5;
    const int lane = tid & 31;
    const uint32_t* lp = g_logits_bf + (size_t)row * (M / 2);   // 32768 u32

    __shared__ int   s_cnt;
    __shared__ int   s_idx[CAND_CAP];
    __shared__ float s_val[CAND_CAP];

    // pass 1: per-thread max over 64 bf16 (8 uint4)
    float mx = -INFINITY;
#pragma unroll
    for (int it = 0; it < 8; it++) {
        uint4 v = *reinterpret_cast<const uint4*>(lp + (size_t)(tid + it * 1024) * 4);
#pragma unroll
        for (int w = 0; w < 4; w++) {
            uint32_t pw = (w == 0) ? v.x : (w == 1) ? v.y : (w == 2) ? v.z : v.w;
            float2 f = __bfloat1622float2(*reinterpret_cast<__nv_bfloat162*>(&pw));
            mx = fmaxf(mx, fmaxf(f.x, f.y));
        }
    }
    uint32_t mymono = mono16_of(mx);

    // 16-bit ballot-bisect: largest T with count(slice_max > T) >= 16
    uint32_t lo = 0u, hi = 0xFFFFu;
    for (int it = 0; it < 16; it++) {
        uint32_t mid = (lo + hi + 1) >> 1;
        int cnt = __syncthreads_count(mymono > mid);
        if (cnt >= NUM_TOP) lo = mid; else hi = mid - 1;
    }
    // stored 16th-largest > float_of_mono16(lo); margin covers bf16 gemm + storage err
    const float thr = float_of_mono16(lo) - 1.5f;

    if (tid == 0) s_cnt = 0;
    __syncthreads();

    // pass 2: compact candidate indices into smem (L2-resident re-read)
#pragma unroll
    for (int it = 0; it < 8; it++) {
        int f4 = tid + it * 1024;
        uint4 v = *reinterpret_cast<const uint4*>(lp + (size_t)f4 * 4);
        int base = f4 * 8;
#pragma unroll
        for (int w = 0; w < 4; w++) {
            uint32_t pw = (w == 0) ? v.x : (w == 1) ? v.y : (w == 2) ? v.z : v.w;
            float2 f = __bfloat1622float2(*reinterpret_cast<__nv_bfloat162*>(&pw));
            if (f.x > thr) {
                int pos = atomicAdd(&s_cnt, 1);
                if (pos < CAND_CAP) s_idx[pos] = base + w * 2;
            }
            if (f.y > thr) {
                int pos = atomicAdd(&s_cnt, 1);
                if (pos < CAND_CAP) s_idx[pos] = base + w * 2 + 1;
            }
        }
    }
    __syncthreads();
    const int cnt = (s_cnt < CAND_CAP) ? s_cnt : CAND_CAP;

    // exact fp32 rescore: one warp per candidate, 32 warps
    float qv[8];
#pragma unroll
    for (int u = 0; u < 8; u++) qv[u] = q[(size_t)row * D + lane + 32 * u];

    for (int c = warp; c < cnt; c += 32) {
        const float* kp = key + (size_t)s_idx[c] * D;
        float s = 0.0f;
#pragma unroll
        for (int u = 0; u < 8; u++) s = fmaf(qv[u], kp[lane + 32 * u], s);
#pragma unroll
        for (int o = 16; o; o >>= 1) s += __shfl_xor_sync(0xFFFFFFFFu, s, o);
        if (lane == 0) s_val[c] = s;
    }
    __syncthreads();

    // exact top-16 over (val desc, idx asc)
    if (tid == 0) {
        float lv[NUM_TOP]; int li[NUM_TOP];
#pragma unroll
        for (int j = 0; j < NUM_TOP; j++) { lv[j] = -INFINITY; li[j] = 0x7FFFFFFF; }
        for (int c = 0; c < cnt; c++) {
            float v = s_val[c]; int idx = s_idx[c];
            bool better_last = (v > lv[NUM_TOP - 1]) ||
                               (v == lv[NUM_TOP - 1] && idx < li[NUM_TOP - 1]);
            if (better_last) {
                float cv = v; int ci = idx;
#pragma unroll
                for (int j = 0; j < NUM_TOP; j++) {
                    if (cv > lv[j] || (cv == lv[j] && ci < li[j])) {
                        float tv = lv[j]; lv[j] = cv; cv = tv;
                        int ti = li[j]; li[j] = ci; ci = ti;
                    }
                }
            }
        }
#pragma unroll
        for (int j = 0; j < NUM_TOP; j++) {
            g_top_val[row * NUM_TOP + j] = lv[j];
            g_top_idx[row * NUM_TOP + j] = li[j];
            g_excluded[li[j]] = 1;               // fused exclusion scatter
        }
    }
}

// ---------------- threefry2x32, partitionable: bits = x0out ^ x1out ----------------
__device__ __forceinline__ uint32_t rotl32(uint32_t x, int r) { return (x << r) | (x >> (32 - r)); }

#define TF_GROUP(a,b,c,d) \
    x0 += x1; x1 = rotl32(x1, a); x1 ^= x0; \
    x0 += x1; x1 = rotl32(x1, b); x1 ^= x0; \
    x0 += x1; x1 = rotl32(x1, c); x1 ^= x0; \
    x0 += x1; x1 = rotl32(x1, d); x1 ^= x0;

__global__ __launch_bounds__(1024) void rand_part_kernel() {
    const int tid = threadIdx.x;
    const int base = blockIdx.x * (M / RAND_BLOCKS);   // 2048 per block
    const uint32_t ks0 = 0u, ks1 = 42u, ks2 = 0x1BD11BDAu ^ 42u;

    unsigned long long best[NUM_RAND];
#pragma unroll
    for (int j = 0; j < NUM_RAND; j++) best[j] = 0xFFFFFFFFFFFFFFFFull;

    for (int i = base + tid; i < base + M / RAND_BLOCKS; i += 1024) {
        uint32_t x0 = 0u + ks0;            // counts_hi = 0
        uint32_t x1 = (uint32_t)i + ks1;   // counts_lo = i
        TF_GROUP(13, 15, 26, 6);  x0 += ks1; x1 += ks2 + 1u;
        TF_GROUP(17, 29, 16, 24); x0 += ks2; x1 += ks0 + 2u;
        TF_GROUP(13, 15, 26, 6);  x0 += ks0; x1 += ks1 + 3u;
        TF_GROUP(17, 29, 16, 24); x0 += ks1; x1 += ks2 + 4u;
        TF_GROUP(13, 15, 26, 6);  x0 += ks2; x1 += ks0 + 5u;
        uint32_t bits = x0 ^ x1;           // partitionable <64-bit combine
        uint32_t fb = g_excluded[i] ? 0x7F800000u : ((bits >> 9) | 0x3F800000u);
        unsigned long long kv = ((unsigned long long)fb << 32) | (uint32_t)i;
        if (kv < best[NUM_RAND - 1]) {
            unsigned long long c = kv;
#pragma unroll
            for (int j = 0; j < NUM_RAND; j++) {
                if (c < best[j]) { unsigned long long t = best[j]; best[j] = c; c = t; }
            }
        }
    }

    __shared__ unsigned long long sk[1024 * NUM_RAND];
#pragma unroll
    for (int j = 0; j < NUM_RAND; j++) sk[tid * NUM_RAND + j] = best[j];
    __syncthreads();

    for (int s = 512; s >= 1; s >>= 1) {
        if (tid < s) {
            const unsigned long long* a = &sk[tid * NUM_RAND];
            const unsigned long long* b = &sk[(tid + s) * NUM_RAND];
            unsigned long long o[NUM_RAND];
            int p = 0, qq = 0;
#pragma unroll
            for (int j = 0; j < NUM_RAND; j++) {
                bool ta;
                if (p >= NUM_RAND)       ta = false;
                else if (qq >= NUM_RAND) ta = true;
                else                     ta = (a[p] < b[qq]);
                if (ta) { o[j] = a[p]; p++; }
                else    { o[j] = b[qq]; qq++; }
            }
#pragma unroll
            for (int j = 0; j < NUM_RAND; j++) sk[tid * NUM_RAND + j] = o[j];
        }
        __syncthreads();
    }

    if (tid < NUM_RAND) g_rand_part[blockIdx.x * NUM_RAND + tid] = sk[tid];
}

// ---------------- composite + softmax + output (rand merge fused) ----------------
__global__ __launch_bounds__(128) void final_kernel(const float* __restrict__ q,
                                                    const float* __restrict__ key,
                                                    float* __restrict__ out) {
    const int row = blockIdx.x;
    const int tid = threadIdx.x;
    const int warp = tid >> 5;
    const int lane = tid & 31;
    __shared__ float rl[NUM_RAND];
    __shared__ int   ri[NUM_RAND];

    // every block deterministically merges the rand partials (128 u64, L2-hot)
    if (tid == 0) {
        unsigned long long best[NUM_RAND];
#pragma unroll
        for (int j = 0; j < NUM_RAND; j++) best[j] = 0xFFFFFFFFFFFFFFFFull;
        for (int i = 0; i < RAND_BLOCKS * NUM_RAND; i++) {
            unsigned long long c = g_rand_part[i];
            if (c < best[NUM_RAND - 1]) {
#pragma unroll
                for (int j = 0; j < NUM_RAND; j++) {
                    if (c < best[j]) { unsigned long long t = best[j]; best[j] = c; c = t; }
                }
            }
        }
#pragma unroll
        for (int j = 0; j < NUM_RAND; j++) ri[j] = (int)(best[j] & 0xFFFFFFFFu);
    }
    __syncthreads();

    // one warp per rand dot (exact fp32)
    const float* qp = q + (size_t)row * D;
    {
        int idx = ri[warp];
        const float* kp = key + (size_t)idx * D;
        float s = 0.0f;
#pragma unroll
        for (int u = 0; u < 8; u++) s = fmaf(qp[lane + 32 * u], kp[lane + 32 * u], s);
#pragma unroll
        for (int o = 16; o; o >>= 1) s += __shfl_xor_sync(0xFFFFFFFFu, s, o);
        if (lane == 0) rl[warp] = s;
    }
    __syncthreads();

    if (tid == 0) {
        const int NC = NUM_TOP + NUM_RAND;  // 20
        float cl[NC]; int ci[NC];
#pragma unroll
        for (int j = 0; j < NUM_TOP; j++) {
            cl[j] = g_top_val[row * NUM_TOP + j];
            ci[j] = g_top_idx[row * NUM_TOP + j];
        }
#pragma unroll
        for (int j = 0; j < NUM_RAND; j++) {
            cl[NUM_TOP + j] = rl[j];
            ci[NUM_TOP + j] = ri[j];
        }
        float mx = cl[0];
#pragma unroll
        for (int j = 1; j < NC; j++) mx = fmaxf(mx, cl[j]);
        float e[NC]; float sum = 0.0f;
#pragma unroll
        for (int j = 0; j < NC; j++) { e[j] = expf(cl[j] - mx); sum += e[j]; }
        float inv = 1.0f / sum;
#pragma unroll
        for (int j = 0; j < NC; j++) {
            out[row * NC + j] = (float)ci[j];                 // composite_idx (as f32)
            out[R * NC + row * NC + j] = e[j] * inv;          // composite_probs
        }
    }
}

// ---------------- launcher ----------------
extern "C" void kernel_launch(void* const* d_in, const int* in_sizes, int n_in,
                              void* d_out, int out_size) {
    const float* q   = (const float*)d_in[0];   // (8,16,256)
    const float* key = (const float*)d_in[1];   // (65536,256)
    float* out = (float*)d_out;

    init_kernel<<<256, 256>>>(q);
    gemm_bf16_kernel<<<M / GCOLS, 256>>>(key);
    candrescore_kernel<<<R, 1024>>>(q, key);
    rand_part_kernel<<<RAND_BLOCKS, 1024>>>();
    final_kernel<<<R, 128>>>(q, key, out);
}